// round 16
// baseline (speedup 1.0000x reference)
#include <cuda_runtime.h>
#include <cuda_bf16.h>
#include <math.h>
#include <cstdint>

// ---------------- Problem constants ----------------
constexpr int B   = 2;
constexpr int S   = 2048;
constexpr int D   = 2560;
constexpr int H   = 8;
constexpr int HKV = 4;
constexpr int HD  = 256;
constexpr int NTOK = B * S;                 // 4096
constexpr int QKV_COLS = H*HD + 2*HKV*HD;   // 4096
constexpr float EPS = 1e-6f;
constexpr float SCALING = 0.0625f;
constexpr float SOFTCAP = 4096.0f;
constexpr float NEGBIG = -1e9f;

constexpr int K1 = D;          // 2560
constexpr int K2 = H * HD;     // 2048

// ---------------- Scratch (device globals) ----------------
__device__ float g_qkv[(size_t)NTOK * QKV_COLS];
__device__ __nv_bfloat16 g_xh [(size_t)NTOK * K1];
__device__ __nv_bfloat16 g_xl [(size_t)NTOK * K1];
__device__ __nv_bfloat16 g_wh [(size_t)QKV_COLS * K1];
__device__ __nv_bfloat16 g_wl [(size_t)QKV_COLS * K1];
__device__ __nv_bfloat16 g_ah [(size_t)NTOK * K2];
__device__ __nv_bfloat16 g_al [(size_t)NTOK * K2];
__device__ __nv_bfloat16 g_owh[(size_t)D * K2];
__device__ __nv_bfloat16 g_owl[(size_t)D * K2];
__device__ __nv_bfloat16 g_qh[(size_t)B * H   * S * HD];
__device__ __nv_bfloat16 g_ql[(size_t)B * H   * S * HD];
__device__ __nv_bfloat16 g_kh[(size_t)B * HKV * S * HD];
__device__ __nv_bfloat16 g_kl[(size_t)B * HKV * S * HD];
__device__ __nv_bfloat16 g_vh[(size_t)B * HKV * S * HD];
__device__ __nv_bfloat16 g_vl[(size_t)B * HKV * S * HD];

// ================= helpers =================
__device__ __forceinline__ uint32_t smem_to_u32(const void* p) {
    uint32_t a;
    asm("{ .reg .u64 t; cvta.to.shared.u64 t, %1; cvt.u32.u64 %0, t; }" : "=r"(a) : "l"(p));
    return a;
}

__device__ __forceinline__ void cp16(uint32_t s, const void* g) {
    asm volatile("cp.async.cg.shared.global [%0], [%1], 16;\n" :: "r"(s), "l"(g));
}
#define CP_COMMIT() asm volatile("cp.async.commit_group;\n" ::: "memory")
template<int N> __device__ __forceinline__ void cp_wait() {
    asm volatile("cp.async.wait_group %0;\n" :: "n"(N) : "memory");
}

__device__ __forceinline__ void ldm_x4(uint32_t* r, uint32_t addr) {
    asm volatile("ldmatrix.sync.aligned.m8n8.x4.shared.b16 {%0,%1,%2,%3}, [%4];"
        : "=r"(r[0]), "=r"(r[1]), "=r"(r[2]), "=r"(r[3]) : "r"(addr));
}
__device__ __forceinline__ void ldm_x4_t(uint32_t* r, uint32_t addr) {
    asm volatile("ldmatrix.sync.aligned.m8n8.x4.trans.shared.b16 {%0,%1,%2,%3}, [%4];"
        : "=r"(r[0]), "=r"(r[1]), "=r"(r[2]), "=r"(r[3]) : "r"(addr));
}
// NOTE: non-volatile — pure register op, deps carried by constraints; lets ptxas
// software-pipeline around the ~24cyc MMA latency.
__device__ __forceinline__ void mma_bf16(float* d, const uint32_t* a, uint32_t b0, uint32_t b1) {
    asm("mma.sync.aligned.m16n8k16.row.col.f32.bf16.bf16.f32 "
        "{%0,%1,%2,%3}, {%4,%5,%6,%7}, {%8,%9}, {%0,%1,%2,%3};"
        : "+f"(d[0]), "+f"(d[1]), "+f"(d[2]), "+f"(d[3])
        : "r"(a[0]), "r"(a[1]), "r"(a[2]), "r"(a[3]), "r"(b0), "r"(b1));
}
__device__ __forceinline__ uint32_t pack_bf16(float a, float b) {
    __nv_bfloat162 t = __floats2bfloat162_rn(a, b);
    return *(uint32_t*)&t;
}

// ================ Split-precision conversion kernels ================
__device__ __forceinline__ void split4(float4 v, __nv_bfloat16* h, __nv_bfloat16* l) {
    h[0] = __float2bfloat16(v.x); l[0] = __float2bfloat16(v.x - __bfloat162float(h[0]));
    h[1] = __float2bfloat16(v.y); l[1] = __float2bfloat16(v.y - __bfloat162float(h[1]));
    h[2] = __float2bfloat16(v.z); l[2] = __float2bfloat16(v.z - __bfloat162float(h[2]));
    h[3] = __float2bfloat16(v.w); l[3] = __float2bfloat16(v.w - __bfloat162float(h[3]));
}
__device__ __forceinline__ void st8(__nv_bfloat16* p, const __nv_bfloat16* v) {
    *(uint2*)p = *(const uint2*)v;
}

__global__ __launch_bounds__(256) void conv_split(const float* __restrict__ src,
                                                  __nv_bfloat16* __restrict__ dh,
                                                  __nv_bfloat16* __restrict__ dl,
                                                  long tot4)
{
    long idx = (long)blockIdx.x * 256 + threadIdx.x;
    if (idx >= tot4) return;
    float4 v = ((const float4*)src)[idx];
    __nv_bfloat16 h[4], l[4];
    split4(v, h, l);
    st8(dh + idx * 4, h);
    st8(dl + idx * 4, l);
}

__global__ __launch_bounds__(256) void conv_split_qkv(const float* __restrict__ qw,
                                                      const float* __restrict__ kw,
                                                      const float* __restrict__ vw,
                                                      __nv_bfloat16* __restrict__ dh,
                                                      __nv_bfloat16* __restrict__ dl)
{
    const int kq = K1 >> 2;
    long idx = (long)blockIdx.x * 256 + threadIdx.x;
    long tot = (long)QKV_COLS * kq;
    if (idx >= tot) return;
    long r = idx / kq; int k4 = (int)(idx - r * kq);
    const float* src = (r < 2048) ? qw + r * (long)K1
                     : (r < 3072) ? kw + (r - 2048) * (long)K1
                                  : vw + (r - 3072) * (long)K1;
    float4 v = ((const float4*)src)[k4];
    __nv_bfloat16 h[4], l[4];
    split4(v, h, l);
    st8(dh + idx * 4, h);
    st8(dl + idx * 4, l);
}

// ================ bf16x3 HMMA GEMM, BK=32, 2 CTAs/SM ================
constexpr int G_STAGE = 32768;
constexpr int GEMM_SMEM = 3 * G_STAGE;   // 98304

__device__ __forceinline__ uint32_t phz(int row) { return ((uint32_t)(row >> 1) & 3u) << 4; }

__device__ __forceinline__ void load_chunk4(const char* Ah, const char* Al,
                                            const char* Bh, const char* Bl,
                                            size_t rowbytes, uint32_t smem_base,
                                            int stage, long kbyte, int tid)
{
    uint32_t s0 = smem_base + (uint32_t)stage * G_STAGE;
#pragma unroll
    for (int p = 0; p < 2; p++) {
        int idx = p * 256 + tid;
        int row = idx >> 2, j = idx & 3;
        uint32_t off = (uint32_t)row * 64 + (((uint32_t)j * 16) ^ phz(row));
        size_t go = (size_t)row * rowbytes + kbyte + j * 16;
        cp16(s0 + off,         Ah + go);
        cp16(s0 + 8192 + off,  Al + go);
        cp16(s0 + 16384 + off, Bh + go);
        cp16(s0 + 24576 + off, Bl + go);
    }
    CP_COMMIT();
}

__global__ __launch_bounds__(256, 2) void gemm_bf16x3(const __nv_bfloat16* __restrict__ Ahp,
                                                      const __nv_bfloat16* __restrict__ Alp,
                                                      const __nv_bfloat16* __restrict__ Bhp,
                                                      const __nv_bfloat16* __restrict__ Blp,
                                                      float* __restrict__ C,
                                                      int K, int Ntot)
{
    extern __shared__ char smem[];
    const uint32_t smem_base = smem_to_u32(smem);
    const int tid = threadIdx.x;
    const int wid = tid >> 5, lane = tid & 31;
    const int wm = wid & 1;
    const int wn = wid >> 1;
    const int n0 = blockIdx.x * 128;
    const int m0 = blockIdx.y * 128;

    const size_t rowbytes = (size_t)K * 2;
    const char* Ah = (const char*)Ahp + (size_t)m0 * rowbytes;
    const char* Al = (const char*)Alp + (size_t)m0 * rowbytes;
    const char* Bh = (const char*)Bhp + (size_t)n0 * rowbytes;
    const char* Bl = (const char*)Blp + (size_t)n0 * rowbytes;
    const int C_chunks = K / 32;

    load_chunk4(Ah, Al, Bh, Bl, rowbytes, smem_base, 0, 0, tid);
    load_chunk4(Ah, Al, Bh, Bl, rowbytes, smem_base, 1, 64, tid);
    load_chunk4(Ah, Al, Bh, Bl, rowbytes, smem_base, 2, 128, tid);

    float acc[4][4][4];
#pragma unroll
    for (int i = 0; i < 4; i++)
#pragma unroll
        for (int j = 0; j < 4; j++)
#pragma unroll
            for (int q = 0; q < 4; q++) acc[i][j][q] = 0.f;

    const int a_row_l = (lane & 15);
    const uint32_t a_hi = (uint32_t)(lane >> 4) * 16;
    const int b_row_l = (lane & 7) + ((lane >> 4) & 1) * 8;
    const uint32_t b_hi = (uint32_t)((lane >> 3) & 1) * 16;

    for (int c = 0; c < C_chunks; c++) {
        const int s = c % 3;
        if (c + 2 < C_chunks)      cp_wait<2>();
        else if (c + 1 < C_chunks) cp_wait<1>();
        else                       cp_wait<0>();
        __syncthreads();

        const uint32_t sah = smem_base + (uint32_t)s * G_STAGE;
        const uint32_t sal = sah + 8192;
        const uint32_t sbh = sah + 16384;
        const uint32_t sbl = sah + 24576;

#pragma unroll
        for (int ks = 0; ks < 2; ks++) {
            uint32_t bh[2][4], bl[2][4];
#pragma unroll
            for (int nb = 0; nb < 2; nb++) {
                int row = wn * 32 + nb * 16 + b_row_l;
                uint32_t kb = ((uint32_t)(ks * 32) + b_hi) ^ phz(row);
                ldm_x4(bh[nb], sbh + (uint32_t)row * 64 + kb);
                ldm_x4(bl[nb], sbl + (uint32_t)row * 64 + kb);
            }
            uint32_t ah_f[4][4], al_f[4][4];
#pragma unroll
            for (int mf = 0; mf < 4; mf++) {
                int row = wm * 64 + mf * 16 + a_row_l;
                uint32_t kb = ((uint32_t)(ks * 32) + a_hi) ^ phz(row);
                ldm_x4(ah_f[mf], sah + (uint32_t)row * 64 + kb);
                ldm_x4(al_f[mf], sal + (uint32_t)row * 64 + kb);
            }
            // term 1: hi*hi — 16 independent accumulators
#pragma unroll
            for (int mf = 0; mf < 4; mf++)
#pragma unroll
                for (int nf = 0; nf < 4; nf++)
                    mma_bf16(acc[mf][nf], ah_f[mf], bh[nf >> 1][(nf & 1) * 2], bh[nf >> 1][(nf & 1) * 2 + 1]);
            // term 2: hi*lo — same acc set, reuse distance 16
#pragma unroll
            for (int mf = 0; mf < 4; mf++)
#pragma unroll
                for (int nf = 0; nf < 4; nf++)
                    mma_bf16(acc[mf][nf], ah_f[mf], bl[nf >> 1][(nf & 1) * 2], bl[nf >> 1][(nf & 1) * 2 + 1]);
            // term 3: lo*hi
#pragma unroll
            for (int mf = 0; mf < 4; mf++)
#pragma unroll
                for (int nf = 0; nf < 4; nf++)
                    mma_bf16(acc[mf][nf], al_f[mf], bh[nf >> 1][(nf & 1) * 2], bh[nf >> 1][(nf & 1) * 2 + 1]);
        }
        __syncthreads();
        if (c + 3 < C_chunks)
            load_chunk4(Ah, Al, Bh, Bl, rowbytes, smem_base, s, (long)(c + 3) * 64, tid);
    }

    const int er = lane >> 2;
    const int ec = (lane & 3) * 2;
#pragma unroll
    for (int mf = 0; mf < 4; mf++) {
        const int rbase = m0 + wm * 64 + mf * 16 + er;
#pragma unroll
        for (int nf = 0; nf < 4; nf++) {
            const int cbase = n0 + wn * 32 + nf * 8 + ec;
            float* p0 = C + (size_t)rbase * Ntot + cbase;
            float* p1 = C + (size_t)(rbase + 8) * Ntot + cbase;
            *(float2*)p0 = make_float2(acc[mf][nf][0], acc[mf][nf][1]);
            *(float2*)p1 = make_float2(acc[mf][nf][2], acc[mf][nf][3]);
        }
    }
}

// ---------------- RMSNorm + RoPE: warp-per-head-row (unchanged) ----------------
__global__ __launch_bounds__(256) void norm_rope_kernel(
    const float* __restrict__ cosp, const float* __restrict__ sinp,
    const float* __restrict__ qn_w, const float* __restrict__ kn_w)
{
    const int token = blockIdx.x;
    const int w = threadIdx.x >> 5, lane = threadIdx.x & 31;
    const int slot = blockIdx.y * 8 + w;
    const int b = token / S;
    const int s = token % S;

    const float* row = g_qkv + (size_t)token * QKV_COLS;
    const float* src = (slot < 8)  ? row + slot * HD
                     : (slot < 12) ? row + 2048 + (slot - 8) * HD
                                   : row + 3072 + (slot - 12) * HD;
    const int d0 = lane * 4;
    float4 x0 = *(const float4*)(src + d0);
    float4 x1 = *(const float4*)(src + 128 + d0);

    if (slot >= 12) {
        size_t o = (((size_t)b * HKV + (slot - 12)) * S + s) * HD;
        __nv_bfloat16 h[4], l[4];
        split4(x0, h, l); st8(g_vh + o + d0, h); st8(g_vl + o + d0, l);
        split4(x1, h, l); st8(g_vh + o + 128 + d0, h); st8(g_vl + o + 128 + d0, l);
        return;
    }

    float ss = x0.x*x0.x + x0.y*x0.y + x0.z*x0.z + x0.w*x0.w
             + x1.x*x1.x + x1.y*x1.y + x1.z*x1.z + x1.w*x1.w;
#pragma unroll
    for (int o = 16; o > 0; o >>= 1) ss += __shfl_xor_sync(0xffffffffu, ss, o);
    const float scale = rsqrtf(ss * (1.0f / HD) + EPS);

    const float* nw = (slot < 8) ? qn_w : kn_w;
    float4 nw0 = *(const float4*)(nw + d0);
    float4 nw1 = *(const float4*)(nw + 128 + d0);
    float4 xn0, xn1;
    xn0.x = x0.x * scale * (1.0f + nw0.x); xn0.y = x0.y * scale * (1.0f + nw0.y);
    xn0.z = x0.z * scale * (1.0f + nw0.z); xn0.w = x0.w * scale * (1.0f + nw0.w);
    xn1.x = x1.x * scale * (1.0f + nw1.x); xn1.y = x1.y * scale * (1.0f + nw1.y);
    xn1.z = x1.z * scale * (1.0f + nw1.z); xn1.w = x1.w * scale * (1.0f + nw1.w);

    const size_t csi = ((size_t)b * S + s) * HD;
    float4 c0 = *(const float4*)(cosp + csi + d0);
    float4 c1 = *(const float4*)(cosp + csi + 128 + d0);
    float4 s0 = *(const float4*)(sinp + csi + d0);
    float4 s1 = *(const float4*)(sinp + csi + 128 + d0);

    float4 o0, o1;
    o0.x = xn0.x * c0.x - xn1.x * s0.x;  o0.y = xn0.y * c0.y - xn1.y * s0.y;
    o0.z = xn0.z * c0.z - xn1.z * s0.z;  o0.w = xn0.w * c0.w - xn1.w * s0.w;
    o1.x = xn1.x * c1.x + xn0.x * s1.x;  o1.y = xn1.y * c1.y + xn0.y * s1.y;
    o1.z = xn1.z * c1.z + xn0.z * s1.z;  o1.w = xn1.w * c1.w + xn0.w * s1.w;

    __nv_bfloat16 h[4], l[4];
    if (slot < 8) {
        size_t o = (((size_t)b * H + slot) * S + s) * HD;
        split4(o0, h, l); st8(g_qh + o + d0, h); st8(g_ql + o + d0, l);
        split4(o1, h, l); st8(g_qh + o + 128 + d0, h); st8(g_ql + o + 128 + d0, l);
    } else {
        size_t o = (((size_t)b * HKV + (slot - 8)) * S + s) * HD;
        split4(o0, h, l); st8(g_kh + o + d0, h); st8(g_kl + o + d0, l);
        split4(o1, h, l); st8(g_kh + o + 128 + d0, h); st8(g_kl + o + 128 + d0, l);
    }
}

// ---------------- Flash attention v2 + poly softcap, MMA-reordered ----------------
constexpr int FLASH2_SMEM = 196608;

__global__ __launch_bounds__(128) void flash_mma()
{
    extern __shared__ char fsm[];
    const uint32_t sb0 = smem_to_u32(fsm);
    const uint32_t sQh = sb0, sQl = sb0 + 32768;

    const int qt = gridDim.x - 1 - blockIdx.x;
    const int h  = blockIdx.y;
    const int b  = blockIdx.z;
    const int q0 = qt * 64;
    const int hk = h >> 1;

    const int tid = threadIdx.x, warp = tid >> 5, lane = tid & 31;

    const __nv_bfloat16* Qhp = g_qh + (((size_t)b * H   + h ) * S + q0) * HD;
    const __nv_bfloat16* Qlp = g_ql + (((size_t)b * H   + h ) * S + q0) * HD;
    const __nv_bfloat16* Khp = g_kh + (((size_t)b * HKV + hk) * S) * HD;
    const __nv_bfloat16* Klp = g_kl + (((size_t)b * HKV + hk) * S) * HD;
    const __nv_bfloat16* Vhp = g_vh + (((size_t)b * HKV + hk) * S) * HD;
    const __nv_bfloat16* Vlp = g_vl + (((size_t)b * HKV + hk) * S) * HD;

    for (int u = tid; u < 2048; u += 128) {
        int row = u >> 5, c = u & 31;
        uint32_t off = (uint32_t)row * 512 + (((uint32_t)c * 16) ^ (((uint32_t)row & 7) << 4));
        cp16(sQh + off, Qhp + (size_t)row * HD + c * 8);
        cp16(sQl + off, Qlp + (size_t)row * HD + c * 8);
    }
    CP_COMMIT();

    const int ntiles = 2 * (qt + 1);

#pragma unroll 1
    for (int pt = 0; pt < 2; pt++) {
        uint32_t sB = sb0 + 65536 + pt * 65536;
        int j0 = pt * 32;
        for (int u = tid; u < 1024; u += 128) {
            int row = u >> 5, c = u & 31;
            uint32_t off = (uint32_t)row * 512 + (((uint32_t)c * 16) ^ (((uint32_t)row & 7) << 4));
            size_t g = (size_t)(j0 + row) * HD + c * 8;
            cp16(sB + off,         Khp + g);
            cp16(sB + 16384 + off, Klp + g);
            cp16(sB + 32768 + off, Vhp + g);
            cp16(sB + 49152 + off, Vlp + g);
        }
        CP_COMMIT();
    }

    float acc[32][4];
#pragma unroll
    for (int i = 0; i < 32; i++) { acc[i][0]=0.f; acc[i][1]=0.f; acc[i][2]=0.f; acc[i][3]=0.f; }
    float mrow0 = -1e30f, mrow1 = -1e30f, lrow0 = 0.f, lrow1 = 0.f;

    const int rA = q0 + warp * 16 + (lane >> 2);

    const int arow = warp * 16 + (lane & 15);
    const uint32_t aswz = ((uint32_t)(arow & 7)) << 4;
    const uint32_t asel = (uint32_t)(lane >> 4) * 16;
    const int brow = (lane & 7) + ((lane >> 4) & 1) * 8;
    const uint32_t bswz = ((uint32_t)(brow & 7)) << 4;
    const uint32_t bsel = (uint32_t)((lane >> 3) & 1) * 16;
    const int vlanerow = (lane & 7) + ((lane >> 3) & 1) * 8;
    const uint32_t vdsel = (uint32_t)((lane >> 4) & 1) * 16;

    for (int t = 0; t < ntiles; t++) {
        if (t + 1 < ntiles) cp_wait<1>(); else cp_wait<0>();
        __syncthreads();
        const uint32_t sK = sb0 + 65536 + (t & 1) * 65536;
        const uint32_t sV = sK + 32768;

        float sc[4][4];
#pragma unroll
        for (int i = 0; i < 4; i++) { sc[i][0]=0.f; sc[i][1]=0.f; sc[i][2]=0.f; sc[i][3]=0.f; }

#pragma unroll 4
        for (int kc = 0; kc < 16; kc++) {
            uint32_t kb_a = ((uint32_t)(kc * 32) + asel) ^ aswz;
            uint32_t aq[4], al[4];
            ldm_x4(aq, sQh + (uint32_t)arow * 512 + kb_a);
            ldm_x4(al, sQl + (uint32_t)arow * 512 + kb_a);
            uint32_t kb_b = ((uint32_t)(kc * 32) + bsel) ^ bswz;
            uint32_t bh0[4], bh1[4], bl0[4], bl1[4];
            ldm_x4(bh0, sK + (uint32_t)brow * 512 + kb_b);
            ldm_x4(bh1, sK + (uint32_t)(brow + 16) * 512 + kb_b);
            ldm_x4(bl0, sK + 16384 + (uint32_t)brow * 512 + kb_b);
            ldm_x4(bl1, sK + 16384 + (uint32_t)(brow + 16) * 512 + kb_b);

            // grouped by term: same-sc reuse distance = 4
            mma_bf16(sc[0], aq, bh0[0], bh0[1]);
            mma_bf16(sc[1], aq, bh0[2], bh0[3]);
            mma_bf16(sc[2], aq, bh1[0], bh1[1]);
            mma_bf16(sc[3], aq, bh1[2], bh1[3]);
            mma_bf16(sc[0], al, bh0[0], bh0[1]);
            mma_bf16(sc[1], al, bh0[2], bh0[3]);
            mma_bf16(sc[2], al, bh1[0], bh1[1]);
            mma_bf16(sc[3], al, bh1[2], bh1[3]);
            mma_bf16(sc[0], aq, bl0[0], bl0[1]);
            mma_bf16(sc[1], aq, bl0[2], bl0[3]);
            mma_bf16(sc[2], aq, bl1[0], bl1[1]);
            mma_bf16(sc[3], aq, bl1[2], bl1[3]);
        }

        const int j0 = t * 32;
        float mn0 = mrow0, mn1 = mrow1;
#pragma unroll
        for (int nf = 0; nf < 4; nf++) {
            const int cb = j0 + nf * 8 + (lane & 3) * 2;
#pragma unroll
            for (int e = 0; e < 4; e++) {
                float w = sc[nf][e] * SCALING;
                const float tt = w * (1.0f / SOFTCAP);
                w = w * (1.0f - 0.33333333f * tt * tt);
                const int col = cb + (e & 1);
                const int rowg = (e < 2) ? rA : (rA + 8);
                if (col > rowg) w = NEGBIG;
                sc[nf][e] = w;
                if (e < 2) mn0 = fmaxf(mn0, w); else mn1 = fmaxf(mn1, w);
            }
        }
        mn0 = fmaxf(mn0, __shfl_xor_sync(0xffffffffu, mn0, 1));
        mn0 = fmaxf(mn0, __shfl_xor_sync(0xffffffffu, mn0, 2));
        mn1 = fmaxf(mn1, __shfl_xor_sync(0xffffffffu, mn1, 1));
        mn1 = fmaxf(mn1, __shfl_xor_sync(0xffffffffu, mn1, 2));
        const float corr0 = __expf(mrow0 - mn0);
        const float corr1 = __expf(mrow1 - mn1);
        mrow0 = mn0; mrow1 = mn1;

        float ps0 = 0.f, ps1 = 0.f;
        uint32_t aphi[2][4], aplo[2][4];
#pragma unroll
        for (int f = 0; f < 2; f++) {
#pragma unroll
            for (int hf = 0; hf < 2; hf++) {
                const int nf = 2 * f + hf;
                float p00 = __expf(sc[nf][0] - mn0), p01 = __expf(sc[nf][1] - mn0);
                float p10 = __expf(sc[nf][2] - mn1), p11 = __expf(sc[nf][3] - mn1);
                ps0 += p00 + p01; ps1 += p10 + p11;
                float h00 = __bfloat162float(__float2bfloat16(p00));
                float h01 = __bfloat162float(__float2bfloat16(p01));
                float h10 = __bfloat162float(__float2bfloat16(p10));
                float h11 = __bfloat162float(__float2bfloat16(p11));
                aphi[f][hf * 2 + 0] = pack_bf16(h00, h01);
                aphi[f][hf * 2 + 1] = pack_bf16(h10, h11);
                aplo[f][hf * 2 + 0] = pack_bf16(p00 - h00, p01 - h01);
                aplo[f][hf * 2 + 1] = pack_bf16(p10 - h10, p11 - h11);
            }
        }
        ps0 += __shfl_xor_sync(0xffffffffu, ps0, 1);
        ps0 += __shfl_xor_sync(0xffffffffu, ps0, 2);
        ps1 += __shfl_xor_sync(0xffffffffu, ps1, 1);
        ps1 += __shfl_xor_sync(0xffffffffu, ps1, 2);
        lrow0 = lrow0 * corr0 + ps0;
        lrow1 = lrow1 * corr1 + ps1;

#pragma unroll
        for (int nf = 0; nf < 32; nf++) {
            acc[nf][0] *= corr0; acc[nf][1] *= corr0;
            acc[nf][2] *= corr1; acc[nf][3] *= corr1;
        }

        // PV: interleave the 2 acc targets per g16; non-volatile mma lets ptxas
        // schedule across the fully-unrolled g16 loop.
#pragma unroll
        for (int kf = 0; kf < 2; kf++) {
            const int jrow = kf * 16 + vlanerow;
            const uint32_t vbase = sV + (uint32_t)jrow * 512;
            const uint32_t vswz = ((uint32_t)(jrow & 7)) << 4;
#pragma unroll
            for (int g16 = 0; g16 < 16; g16++) {
                uint32_t dby = ((uint32_t)(g16 * 32) + vdsel) ^ vswz;
                uint32_t vhf[4], vlf[4];
                ldm_x4_t(vhf, vbase + dby);
                ldm_x4_t(vlf, vbase + 16384 + dby);
                mma_bf16(acc[2 * g16],     aphi[kf], vhf[0], vhf[1]);
                mma_bf16(acc[2 * g16 + 1], aphi[kf], vhf[2], vhf[3]);
                mma_bf16(acc[2 * g16],     aplo[kf], vhf[0], vhf[1]);
                mma_bf16(acc[2 * g16 + 1], aplo[kf], vhf[2], vhf[3]);
                mma_bf16(acc[2 * g16],     aphi[kf], vlf[0], vlf[1]);
                mma_bf16(acc[2 * g16 + 1], aphi[kf], vlf[2], vlf[3]);
            }
        }

        __syncthreads();
        if (t + 2 < ntiles) {
            uint32_t sB = sb0 + 65536 + (t & 1) * 65536;
            int j0n = (t + 2) * 32;
            for (int u = tid; u < 1024; u += 128) {
                int row = u >> 5, c = u & 31;
                uint32_t off = (uint32_t)row * 512 + (((uint32_t)c * 16) ^ (((uint32_t)row & 7) << 4));
                size_t g = (size_t)(j0n + row) * HD + c * 8;
                cp16(sB + off,         Khp + g);
                cp16(sB + 16384 + off, Klp + g);
                cp16(sB + 32768 + off, Vhp + g);
                cp16(sB + 49152 + off, Vlp + g);
            }
            CP_COMMIT();
        }
    }

    const float inv0 = 1.0f / lrow0;
    const float inv1 = 1.0f / lrow1;
    const size_t tokA = (size_t)b * S + q0 + warp * 16 + (lane >> 2);
    __nv_bfloat16* rowAh = g_ah + tokA * (size_t)K2 + h * HD;
    __nv_bfloat16* rowAl = g_al + tokA * (size_t)K2 + h * HD;
    __nv_bfloat16* rowBh = g_ah + (tokA + 8) * (size_t)K2 + h * HD;
    __nv_bfloat16* rowBl = g_al + (tokA + 8) * (size_t)K2 + h * HD;
#pragma unroll
    for (int nf = 0; nf < 32; nf++) {
        const int d = nf * 8 + (lane & 3) * 2;
        {
            float v0 = acc[nf][0] * inv0, v1 = acc[nf][1] * inv0;
            float h0 = __bfloat162float(__float2bfloat16(v0));
            float h1 = __bfloat162float(__float2bfloat16(v1));
            *(__nv_bfloat162*)(rowAh + d) = __floats2bfloat162_rn(h0, h1);
            *(__nv_bfloat162*)(rowAl + d) = __floats2bfloat162_rn(v0 - h0, v1 - h1);
        }
        {
            float v0 = acc[nf][2] * inv1, v1 = acc[nf][3] * inv1;
            float h0 = __bfloat162float(__float2bfloat16(v0));
            float h1 = __bfloat162float(__float2bfloat16(v1));
            *(__nv_bfloat162*)(rowBh + d) = __floats2bfloat162_rn(h0, h1);
            *(__nv_bfloat162*)(rowBl + d) = __floats2bfloat162_rn(v0 - h0, v1 - h1);
        }
    }
}

// ---------------- Host launch ----------------
extern "C" void kernel_launch(void* const* d_in, const int* in_sizes, int n_in,
                              void* d_out, int out_size)
{
    const float* x    = (const float*)d_in[0];
    const float* cosp = (const float*)d_in[1];
    const float* sinp = (const float*)d_in[2];
    const float* q_w  = (const float*)d_in[4];
    const float* k_w  = (const float*)d_in[5];
    const float* v_w  = (const float*)d_in[6];
    const float* o_w  = (const float*)d_in[7];
    const float* qn_w = (const float*)d_in[8];
    const float* kn_w = (const float*)d_in[9];
    float* out = (float*)d_out;

    void *p_qkv, *p_xh, *p_xl, *p_wh, *p_wl, *p_ah, *p_al, *p_owh, *p_owl;
    cudaGetSymbolAddress(&p_qkv, g_qkv);
    cudaGetSymbolAddress(&p_xh,  g_xh);
    cudaGetSymbolAddress(&p_xl,  g_xl);
    cudaGetSymbolAddress(&p_wh,  g_wh);
    cudaGetSymbolAddress(&p_wl,  g_wl);
    cudaGetSymbolAddress(&p_ah,  g_ah);
    cudaGetSymbolAddress(&p_al,  g_al);
    cudaGetSymbolAddress(&p_owh, g_owh);
    cudaGetSymbolAddress(&p_owl, g_owl);
    float* qkv = (float*)p_qkv;
    __nv_bfloat16* xh  = (__nv_bfloat16*)p_xh;
    __nv_bfloat16* xl  = (__nv_bfloat16*)p_xl;
    __nv_bfloat16* wh  = (__nv_bfloat16*)p_wh;
    __nv_bfloat16* wl  = (__nv_bfloat16*)p_wl;
    __nv_bfloat16* ah  = (__nv_bfloat16*)p_ah;
    __nv_bfloat16* al  = (__nv_bfloat16*)p_al;
    __nv_bfloat16* owh = (__nv_bfloat16*)p_owh;
    __nv_bfloat16* owl = (__nv_bfloat16*)p_owl;

    cudaFuncSetAttribute(gemm_bf16x3, cudaFuncAttributeMaxDynamicSharedMemorySize, GEMM_SMEM);
    cudaFuncSetAttribute(flash_mma,   cudaFuncAttributeMaxDynamicSharedMemorySize, FLASH2_SMEM);

    // 1) split-convert x and QKV weights
    {
        long tot = (long)NTOK * (K1 / 4);
        conv_split<<<(unsigned)((tot + 255) / 256), 256>>>(x, xh, xl, tot);
        long totw = (long)QKV_COLS * (K1 / 4);
        conv_split_qkv<<<(unsigned)((totw + 255) / 256), 256>>>(q_w, k_w, v_w, wh, wl);
    }
    // 2) QKV projection (3-term HMMA)
    gemm_bf16x3<<<dim3(QKV_COLS / 128, NTOK / 128), 256, GEMM_SMEM>>>(xh, xl, wh, wl, qkv, K1, QKV_COLS);

    // 3) RMSNorm + RoPE + bf16 hi/lo split
    norm_rope_kernel<<<dim3(NTOK, 2), 256>>>(cosp, sinp, qn_w, kn_w);

    // 4) Flash attention v2 (writes g_ah/g_al)
    flash_mma<<<dim3(S / 64, H, B), 128, FLASH2_SMEM>>>();

    // 5) split-convert O weights
    {
        long totw = (long)D * (K2 / 4);
        conv_split<<<(unsigned)((totw + 255) / 256), 256>>>(o_w, owh, owl, totw);
    }
    // 6) O projection
    gemm_bf16x3<<<dim3(D / 128, NTOK / 128), 256, GEMM_SMEM>>>(ah, al, owh, owl, out, K2, D);
}